// round 14
// baseline (speedup 1.0000x reference)
#include <cuda_runtime.h>
#include <math.h>

#define NB   32
#define CC   256
#define HH   64
#define WW   64
#define HW   4096        // 64*64
#define QQ   1600        // 25*64
#define K25  25

// ---------------- scratch (device globals) ---------------------------------
__device__ float                 g_w2sum[CC];
__device__ int                   g_t3i[NB * CC];        // t3 as float bits (>=0)
__device__ __align__(16) float   g_t5[NB * HW];         // p4 * mean_o(t2)
__device__ __align__(16) float   g_t13[NB * HW];        // p13 * t9
__device__ float                 g_t7[NB * K25 * WW];   // [n][k][w]
__device__ float                 g_weff[QQ * K25];      // W10 @ W8
__device__ unsigned              g_Mu[NB * WW];         // max_q t12, order-encoded

__device__ __forceinline__ unsigned encf(float x) {
    unsigned u = __float_as_uint(x);
    return (u & 0x80000000u) ? ~u : (u | 0x80000000u);
}
__device__ __forceinline__ float decf(unsigned u) {
    return __uint_as_float((u & 0x80000000u) ? (u ^ 0x80000000u) : ~u);
}

// ---------------- Kprep: weff (smem-staged), w2sum, zeroing ----------------
#define WQB 8
__global__ void kprep(const float* __restrict__ W2,
                      const float* __restrict__ W8,
                      const float* __restrict__ W10) {
    __shared__ float sW8[CC * K25];        // 25.6 KB
    __shared__ float sW10[WQB * 257];      // 8.2 KB, padded stride 257
    __shared__ float red[256];
    int bid = blockIdx.x, tid = threadIdx.x;

    if (bid < 32) {
        g_t3i[bid * 256 + tid] = 0;
    } else if (bid < 40) {
        g_Mu[(bid - 32) * 256 + tid] = 0u;          // NB*WW = 2048
    } else if (bid < 49) {
        if (bid >= 41) {
            int c0 = (bid - 41) * 32;
            int oc = tid >> 5, c32 = tid & 31;
            float s = 0.f;
            #pragma unroll 8
            for (int j = 0; j < 32; j++)
                s += W2[(oc * 32 + j) * CC + c0 + c32];
            red[tid] = s;
            __syncthreads();
            if (tid < 32) {
                float t = 0.f;
                #pragma unroll
                for (int u = 0; u < 8; u++) t += red[u * 32 + tid];
                g_w2sum[c0 + tid] = t;
            }
            __syncthreads();
        }
    }

    int q0 = bid * WQB;
    for (int i = tid; i < CC * K25; i += 256) sW8[i] = W8[i];
    for (int i = tid; i < WQB * CC; i += 256) {
        int r = i >> 8, o = i & 255;
        sW10[r * 257 + o] = W10[(q0 + r) * CC + o];
    }
    __syncthreads();
    if (tid < WQB * K25) {
        int ql = tid / K25, k = tid % K25;
        float s = 0.f;
        #pragma unroll 4
        for (int o = 0; o < CC; o++)
            s = fmaf(sW10[ql * 257 + o], sW8[o * K25 + k], s);
        g_weff[(q0 + ql) * K25 + k] = s;
    }
}

// ---------------- K1: pass 1 over x -> t5[n,h,w] and t3[n,c] ---------------
// grid = NB*32 blocks (tile of 128 px), 256 threads (8 warps x 32 channels)
__global__ void k1(const float* __restrict__ x, const float* __restrict__ p4) {
    __shared__ float sw[CC];
    __shared__ float sred[8 * 128];
    __shared__ float smax[CC * 33];     // padded: conflict-free both directions
    int n = blockIdx.x >> 5, tile = blockIdx.x & 31;
    int tid = threadIdx.x, warp = tid >> 5, lane = tid & 31;
    sw[tid] = g_w2sum[tid];
    __syncthreads();

    const float4* xb = (const float4*)x + (size_t)n * CC * (HW / 4) + tile * 32;
    float4 a0 = make_float4(0.f, 0.f, 0.f, 0.f);

    #pragma unroll 8
    for (int i = 0; i < 32; i++) {
        int c = warp + 8 * i;
        float4 v = xb[(size_t)c * (HW / 4) + lane];
        v.x = fmaxf(v.x, 0.f); v.y = fmaxf(v.y, 0.f);
        v.z = fmaxf(v.z, 0.f); v.w = fmaxf(v.w, 0.f);
        float wv = sw[c];
        a0.x = fmaf(wv, v.x, a0.x); a0.y = fmaf(wv, v.y, a0.y);
        a0.z = fmaf(wv, v.z, a0.z); a0.w = fmaf(wv, v.w, a0.w);
        smax[c * 33 + lane] = fmaxf(fmaxf(v.x, v.y), fmaxf(v.z, v.w));
    }
    ((float4*)sred)[warp * 32 + lane] = a0;
    __syncthreads();

    if (tid < 128) {
        float s = 0.f;
        #pragma unroll
        for (int w = 0; w < 8; w++) s += sred[w * 128 + tid];
        int px = tile * 128 + tid;
        g_t5[n * HW + px] = s * p4[px] * (1.0f / 256.0f);
    }
    {
        float m = 0.f;
        #pragma unroll
        for (int l = 0; l < 32; l++) m = fmaxf(m, smax[tid * 33 + l]);
        atomicMax(&g_t3i[n * CC + tid], __float_as_int(m));   // relu >= 0
    }
}

// ---------------- K2: dilated-patch column max -> t7[n,k,w] ----------------
__global__ void k2() {
    __shared__ float sm[4 * WW];
    int n = blockIdx.x / K25, k = blockIdx.x % K25;
    int ki = k / 5, kj = k % 5;
    int w = threadIdx.x & 63, hq = threadIdx.x >> 6;
    int cs = w + 3 * kj - 6;
    bool cok = (cs >= 0) && (cs < WW);
    const float* t5n = g_t5 + n * HW;
    float m = -INFINITY;
    #pragma unroll
    for (int hb = 0; hb < 16; hb++) {
        int h = hq * 16 + hb;
        int rs = h + 3 * ki - 6;
        float v = (cok && rs >= 0 && rs < HH) ? t5n[rs * WW + cs] : 0.f;
        m = fmaxf(m, v);
    }
    sm[hq * WW + w] = m;
    __syncthreads();
    if (threadIdx.x < WW) {
        float r = fmaxf(fmaxf(sm[w], sm[WW + w]), fmaxf(sm[2 * WW + w], sm[3 * WW + w]));
        g_t7[n * (K25 * WW) + k * WW + w] = r;
    }
}

// ---------------- Fused K3 + K5dot ----------------------------------------
// 2624 blocks = 64 groups of 41 (25 k3-type + 16 dot-type), 256 threads.
struct S3 { float s7[K25 * WW]; float swf[32 * K25]; float smax[4 * WW]; };
struct S5 { float st3[CC]; float sred[8 * 128]; };

__global__ void __launch_bounds__(256, 6)
k3k5(const float* __restrict__ x, const float* __restrict__ p13) {
    __shared__ __align__(16) char sraw[(sizeof(S3) > sizeof(S5)) ? sizeof(S3) : sizeof(S5)];
    int g = blockIdx.x / 41, r = blockIdx.x % 41;
    int tid = threadIdx.x;

    if (r < 25) {
        // ---------------- k3 body: one (n, k, h-half) ----------------
        S3& sm = *(S3*)sraw;
        int id  = g * 25 + r;            // 0..1599
        int n   = id / 50;
        int rem = id % 50;
        int k   = rem >> 1;
        int h0  = (rem & 1) * 32;

        for (int i = tid; i < K25 * WW; i += 256) sm.s7[i] = g_t7[n * (K25 * WW) + i];
        for (int i = tid; i < 32 * K25; i += 256)
            sm.swf[i] = g_weff[k * (HH * K25) + h0 * K25 + i];
        __syncthreads();

        int w  = tid & 63;
        int hq = tid >> 6;
        float t7c[K25];
        #pragma unroll
        for (int kk = 0; kk < K25; kk++) t7c[kk] = sm.s7[kk * WW + w];

        int ki = k / 5, kj = k % 5;
        int cs = w + 3 * kj - 6;
        bool cok = (cs >= 0) && (cs < WW);
        const float* t5n = g_t5 + n * HW;

        float mymax = -INFINITY;
        for (int hb = 0; hb < 8; hb++) {
            int hl = hq * 8 + hb;
            int h  = h0 + hl;
            float t10 = 0.f;
            const float* wr = sm.swf + hl * K25;
            #pragma unroll
            for (int kk = 0; kk < K25; kk++) t10 = fmaf(wr[kk], t7c[kk], t10);
            float gl = 0.5f * t10 * (1.0f + erff(t10 * 0.70710678118654752f));
            int rs = h + 3 * ki - 6;
            float t6v = (cok && rs >= 0 && rs < HH) ? __ldg(t5n + rs * WW + cs) : 0.f;
            mymax = fmaxf(mymax, t6v + gl);      // exp is monotone: defer it
        }
        sm.smax[hq * WW + w] = mymax;
        __syncthreads();
        if (tid < WW) {
            float m = fmaxf(fmaxf(sm.smax[tid], sm.smax[WW + tid]),
                            fmaxf(sm.smax[2 * WW + tid], sm.smax[3 * WW + tid]));
            atomicMax(&g_Mu[n * WW + tid], encf(m));
        }
    } else {
        // ---------------- k5dot body: t13 = p13 * (t3 . x), 128-px tile ----
        S5& sm = *(S5*)sraw;
        int id = g * 16 + (r - 25);      // 0..1023
        int n = id >> 5, tile = id & 31;
        int warp = tid >> 5, lane = tid & 31;
        sm.st3[tid] = __int_as_float(g_t3i[n * CC + tid]);
        __syncthreads();

        const float4* xb = (const float4*)x + (size_t)n * CC * (HW / 4) + tile * 32;
        float4 a0 = make_float4(0.f, 0.f, 0.f, 0.f);
        #pragma unroll 8
        for (int i = 0; i < 32; i++) {
            int c = warp + 8 * i;
            float4 v = xb[(size_t)c * (HW / 4) + lane];
            float t = sm.st3[c];
            a0.x = fmaf(t, v.x, a0.x); a0.y = fmaf(t, v.y, a0.y);
            a0.z = fmaf(t, v.z, a0.z); a0.w = fmaf(t, v.w, a0.w);
        }
        ((float4*)sm.sred)[warp * 32 + lane] = a0;
        __syncthreads();
        if (tid < 128) {
            float s = 0.f;
            #pragma unroll
            for (int w = 0; w < 8; w++) s += sm.sred[w * 128 + tid];
            int px = tile * 128 + tid;
            g_t13[n * HW + px] = s * p13[px];
        }
    }
}

// ---------------- K5write: broadcast-write all 256 channels ----------------
// grid = NB*32 blocks (tile of 128 px = 2 h-rows), 256 threads
__global__ void k5write(const float* __restrict__ W18, float* __restrict__ out) {
    __shared__ __align__(16) float s13[128];
    __shared__ __align__(16) float st17[WW];
    __shared__ float sW18[CC * 2];     // [c][hr]

    int n = blockIdx.x >> 5, tile = blockIdx.x & 31;
    int tid = threadIdx.x;
    int h0 = tile * 2;

    ((float2*)sW18)[tid] = *(const float2*)(W18 + tid * HH + h0);
    if (tid < 128) s13[tid] = g_t13[n * HW + tile * 128 + tid];
    if (tid < WW) {
        float s = 0.f;
        #pragma unroll
        for (int j = 0; j < 7; j++) {
            int p = tid - 9 + 3 * j;
            if (p >= 0 && p < WW) s += expf(decf(g_Mu[n * WW + p]));
        }
        st17[tid] = s * (1.0f / 7.0f);
    }
    __syncthreads();

    float4* ob = (float4*)out + (size_t)n * CC * (HW / 4) + tile * 32;
    #pragma unroll 8
    for (int j = 0; j < 32; j++) {
        int idx = j * 256 + tid;       // 0..8191
        int c   = idx >> 5;
        int f4  = idx & 31;
        int hr  = f4 >> 4;
        int wq  = f4 & 15;
        float wv   = sW18[c * 2 + hr];
        float4 t   = ((const float4*)s13)[f4];
        float4 t17 = ((const float4*)st17)[wq];
        float4 o;
        o.x = fmaf(-wv, t17.x, t.x);
        o.y = fmaf(-wv, t17.y, t.y);
        o.z = fmaf(-wv, t17.z, t.z);
        o.w = fmaf(-wv, t17.w, t.w);
        ob[(size_t)c * (HW / 4) + f4] = o;
    }
}

// ---------------------------------------------------------------------------
extern "C" void kernel_launch(void* const* d_in, const int* in_sizes, int n_in,
                              void* d_out, int out_size) {
    const float* x   = (const float*)d_in[0];
    const float* W2  = (const float*)d_in[1];
    const float* W8  = (const float*)d_in[2];
    const float* W10 = (const float*)d_in[3];
    const float* W18 = (const float*)d_in[4];
    const float* p4  = (const float*)d_in[5];
    const float* p13 = (const float*)d_in[6];
    float* out = (float*)d_out;

    kprep<<<200, 256>>>(W2, W8, W10);
    k1<<<NB * 32, 256>>>(x, p4);
    k2<<<NB * K25, 256>>>();
    k3k5<<<41 * 64, 256>>>(x, p13);          // k3 (compute) + x.t3 dot (memory)
    k5write<<<NB * 32, 256>>>(W18, out);
}

// round 17
// speedup vs baseline: 1.0074x; 1.0074x over previous
#include <cuda_runtime.h>
#include <math.h>

#define NB   32
#define CC   256
#define HH   64
#define WW   64
#define HW   4096        // 64*64
#define QQ   1600        // 25*64
#define K25  25

// ---------------- scratch (device globals) ---------------------------------
__device__ float                 g_w2sum[CC];
__device__ int                   g_t3i[NB * CC];        // t3 as float bits (>=0)
__device__ __align__(16) float   g_t5[NB * HW];         // p4 * mean_o(t2)
__device__ __align__(16) float   g_t13[NB * HW];        // p13 * t9
__device__ float                 g_t7[NB * K25 * WW];   // [n][k][w]
__device__ float                 g_weff[QQ * K25];      // W10 @ W8
__device__ unsigned              g_Mu[NB * WW];         // max_q t12, order-encoded

__device__ __forceinline__ unsigned encf(float x) {
    unsigned u = __float_as_uint(x);
    return (u & 0x80000000u) ? ~u : (u | 0x80000000u);
}
__device__ __forceinline__ float decf(unsigned u) {
    return __uint_as_float((u & 0x80000000u) ? (u ^ 0x80000000u) : ~u);
}

// ---------------- Kprep: weff (smem-staged), w2sum, zeroing ----------------
#define WQB 8
__global__ void kprep(const float* __restrict__ W2,
                      const float* __restrict__ W8,
                      const float* __restrict__ W10) {
    __shared__ float sW8[CC * K25];        // 25.6 KB
    __shared__ float sW10[WQB * 257];      // 8.2 KB, padded stride 257
    __shared__ float red[256];
    int bid = blockIdx.x, tid = threadIdx.x;

    if (bid < 32) {
        g_t3i[bid * 256 + tid] = 0;
    } else if (bid < 40) {
        g_Mu[(bid - 32) * 256 + tid] = 0u;          // NB*WW = 2048
    } else if (bid < 49) {
        if (bid >= 41) {
            int c0 = (bid - 41) * 32;
            int oc = tid >> 5, c32 = tid & 31;
            float s = 0.f;
            #pragma unroll 8
            for (int j = 0; j < 32; j++)
                s += W2[(oc * 32 + j) * CC + c0 + c32];
            red[tid] = s;
            __syncthreads();
            if (tid < 32) {
                float t = 0.f;
                #pragma unroll
                for (int u = 0; u < 8; u++) t += red[u * 32 + tid];
                g_w2sum[c0 + tid] = t;
            }
            __syncthreads();
        }
    }

    int q0 = bid * WQB;
    for (int i = tid; i < CC * K25; i += 256) sW8[i] = W8[i];
    for (int i = tid; i < WQB * CC; i += 256) {
        int r = i >> 8, o = i & 255;
        sW10[r * 257 + o] = W10[(q0 + r) * CC + o];
    }
    __syncthreads();
    if (tid < WQB * K25) {
        int ql = tid / K25, k = tid % K25;
        float s = 0.f;
        #pragma unroll 4
        for (int o = 0; o < CC; o++)
            s = fmaf(sW10[ql * 257 + o], sW8[o * K25 + k], s);
        g_weff[(q0 + ql) * K25 + k] = s;
    }
}

// ---------------- K1: pass 1 over x -> t5[n,h,w] and t3[n,c] ---------------
// grid = NB*32 blocks (tile of 128 px), 256 threads (8 warps x 32 channels)
__global__ void k1(const float* __restrict__ x, const float* __restrict__ p4) {
    __shared__ float sw[CC];
    __shared__ float sred[8 * 128];
    __shared__ float smax[CC * 33];     // padded: conflict-free both directions
    int n = blockIdx.x >> 5, tile = blockIdx.x & 31;
    int tid = threadIdx.x, warp = tid >> 5, lane = tid & 31;
    sw[tid] = g_w2sum[tid];
    __syncthreads();

    const float4* xb = (const float4*)x + (size_t)n * CC * (HW / 4) + tile * 32;
    float4 a0 = make_float4(0.f, 0.f, 0.f, 0.f);

    #pragma unroll 8
    for (int i = 0; i < 32; i++) {
        int c = warp + 8 * i;
        float4 v = xb[(size_t)c * (HW / 4) + lane];
        v.x = fmaxf(v.x, 0.f); v.y = fmaxf(v.y, 0.f);
        v.z = fmaxf(v.z, 0.f); v.w = fmaxf(v.w, 0.f);
        float wv = sw[c];
        a0.x = fmaf(wv, v.x, a0.x); a0.y = fmaf(wv, v.y, a0.y);
        a0.z = fmaf(wv, v.z, a0.z); a0.w = fmaf(wv, v.w, a0.w);
        smax[c * 33 + lane] = fmaxf(fmaxf(v.x, v.y), fmaxf(v.z, v.w));
    }
    ((float4*)sred)[warp * 32 + lane] = a0;
    __syncthreads();

    if (tid < 128) {
        float s = 0.f;
        #pragma unroll
        for (int w = 0; w < 8; w++) s += sred[w * 128 + tid];
        int px = tile * 128 + tid;
        g_t5[n * HW + px] = s * p4[px] * (1.0f / 256.0f);
    }
    {
        float m = 0.f;
        #pragma unroll
        for (int l = 0; l < 32; l++) m = fmaxf(m, smax[tid * 33 + l]);
        atomicMax(&g_t3i[n * CC + tid], __float_as_int(m));   // relu >= 0
    }
}

// ---------------- K2: dilated-patch column max -> t7[n,k,w] ----------------
__global__ void k2() {
    __shared__ float sm[4 * WW];
    int n = blockIdx.x / K25, k = blockIdx.x % K25;
    int ki = k / 5, kj = k % 5;
    int w = threadIdx.x & 63, hq = threadIdx.x >> 6;
    int cs = w + 3 * kj - 6;
    bool cok = (cs >= 0) && (cs < WW);
    const float* t5n = g_t5 + n * HW;
    float m = -INFINITY;
    #pragma unroll
    for (int hb = 0; hb < 16; hb++) {
        int h = hq * 16 + hb;
        int rs = h + 3 * ki - 6;
        float v = (cok && rs >= 0 && rs < HH) ? t5n[rs * WW + cs] : 0.f;
        m = fmaxf(m, v);
    }
    sm[hq * WW + w] = m;
    __syncthreads();
    if (threadIdx.x < WW) {
        float r = fmaxf(fmaxf(sm[w], sm[WW + w]), fmaxf(sm[2 * WW + w], sm[3 * WW + w]));
        g_t7[n * (K25 * WW) + k * WW + w] = r;
    }
}

// ---------------- Fused K3 + K5dot ----------------------------------------
// 2624 blocks = 64 groups of 41 (25 k3-type + 16 dot-type), 256 threads.
// k3 body: weights in padded smem (stride 26, float2 loads); t7 direct LDG.
struct S3 { float swf[32 * 26]; float smax[4 * WW]; };
struct S5 { float st3[CC]; float sred[8 * 128]; };

__global__ void k3k5(const float* __restrict__ x, const float* __restrict__ p13) {
    __shared__ __align__(16) char sraw[(sizeof(S3) > sizeof(S5)) ? sizeof(S3) : sizeof(S5)];
    int g = blockIdx.x / 41, r = blockIdx.x % 41;
    int tid = threadIdx.x;

    if (r < 25) {
        // ---------------- k3 body: one (n, k, h-half) ----------------
        S3& sm = *(S3*)sraw;
        int id  = g * 25 + r;            // 0..1599
        int n   = id / 50;
        int rem = id % 50;
        int k   = rem >> 1;
        int h0  = (rem & 1) * 32;

        // stage weights, rows padded to 26 floats (104B, 8B-aligned)
        for (int i = tid; i < 32 * K25; i += 256) {
            int hl = i / K25, kk = i - hl * K25;
            sm.swf[hl * 26 + kk] = g_weff[k * (HH * K25) + h0 * K25 + i];
        }
        __syncthreads();

        int w  = tid & 63;
        int hq = tid >> 6;
        // t7 column: 25 coalesced LDG (L2-hot, one-time)
        float t7c[K25];
        const float* t7n = g_t7 + n * (K25 * WW);
        #pragma unroll
        for (int kk = 0; kk < K25; kk++) t7c[kk] = __ldg(t7n + kk * WW + w);

        int ki = k / 5, kj = k % 5;
        int cs = w + 3 * kj - 6;
        bool cok = (cs >= 0) && (cs < WW);
        const float* t5n = g_t5 + n * HW;

        float mymax = -INFINITY;
        for (int hb = 0; hb < 8; hb++) {
            int hl = hq * 8 + hb;
            int h  = h0 + hl;
            const float2* wr2 = (const float2*)(sm.swf + hl * 26);
            float t10 = 0.f;
            #pragma unroll
            for (int j = 0; j < 12; j++) {
                float2 wv = wr2[j];
                t10 = fmaf(wv.x, t7c[2 * j + 0], t10);
                t10 = fmaf(wv.y, t7c[2 * j + 1], t10);
            }
            t10 = fmaf(sm.swf[hl * 26 + 24], t7c[24], t10);
            float gl = 0.5f * t10 * (1.0f + erff(t10 * 0.70710678118654752f));
            int rs = h + 3 * ki - 6;
            float t6v = (cok && rs >= 0 && rs < HH) ? __ldg(t5n + rs * WW + cs) : 0.f;
            mymax = fmaxf(mymax, t6v + gl);      // exp is monotone: defer it
        }
        sm.smax[hq * WW + w] = mymax;
        __syncthreads();
        if (tid < WW) {
            float m = fmaxf(fmaxf(sm.smax[tid], sm.smax[WW + tid]),
                            fmaxf(sm.smax[2 * WW + tid], sm.smax[3 * WW + tid]));
            atomicMax(&g_Mu[n * WW + tid], encf(m));
        }
    } else {
        // ---------------- k5dot body: t13 = p13 * (t3 . x), 128-px tile ----
        S5& sm = *(S5*)sraw;
        int id = g * 16 + (r - 25);      // 0..1023
        int n = id >> 5, tile = id & 31;
        int warp = tid >> 5, lane = tid & 31;
        sm.st3[tid] = __int_as_float(g_t3i[n * CC + tid]);
        __syncthreads();

        const float4* xb = (const float4*)x + (size_t)n * CC * (HW / 4) + tile * 32;
        float4 a0 = make_float4(0.f, 0.f, 0.f, 0.f);
        #pragma unroll 8
        for (int i = 0; i < 32; i++) {
            int c = warp + 8 * i;
            float4 v = xb[(size_t)c * (HW / 4) + lane];
            float t = sm.st3[c];
            a0.x = fmaf(t, v.x, a0.x); a0.y = fmaf(t, v.y, a0.y);
            a0.z = fmaf(t, v.z, a0.z); a0.w = fmaf(t, v.w, a0.w);
        }
        ((float4*)sm.sred)[warp * 32 + lane] = a0;
        __syncthreads();
        if (tid < 128) {
            float s = 0.f;
            #pragma unroll
            for (int w = 0; w < 8; w++) s += sm.sred[w * 128 + tid];
            int px = tile * 128 + tid;
            g_t13[n * HW + px] = s * p13[px];
        }
    }
}

// ---------------- K5write: broadcast-write all 256 channels ----------------
// grid = NB*32 blocks (tile of 128 px = 2 h-rows), 256 threads
__global__ void k5write(const float* __restrict__ W18, float* __restrict__ out) {
    __shared__ __align__(16) float s13[128];
    __shared__ __align__(16) float st17[WW];
    __shared__ float sW18[CC * 2];     // [c][hr]

    int n = blockIdx.x >> 5, tile = blockIdx.x & 31;
    int tid = threadIdx.x;
    int h0 = tile * 2;

    ((float2*)sW18)[tid] = *(const float2*)(W18 + tid * HH + h0);
    if (tid < 128) s13[tid] = g_t13[n * HW + tile * 128 + tid];
    if (tid < WW) {
        float s = 0.f;
        #pragma unroll
        for (int j = 0; j < 7; j++) {
            int p = tid - 9 + 3 * j;
            if (p >= 0 && p < WW) s += expf(decf(g_Mu[n * WW + p]));
        }
        st17[tid] = s * (1.0f / 7.0f);
    }
    __syncthreads();

    float4* ob = (float4*)out + (size_t)n * CC * (HW / 4) + tile * 32;
    #pragma unroll 8
    for (int j = 0; j < 32; j++) {
        int idx = j * 256 + tid;       // 0..8191
        int c   = idx >> 5;
        int f4  = idx & 31;
        int hr  = f4 >> 4;
        int wq  = f4 & 15;
        float wv   = sW18[c * 2 + hr];
        float4 t   = ((const float4*)s13)[f4];
        float4 t17 = ((const float4*)st17)[wq];
        float4 o;
        o.x = fmaf(-wv, t17.x, t.x);
        o.y = fmaf(-wv, t17.y, t.y);
        o.z = fmaf(-wv, t17.z, t.z);
        o.w = fmaf(-wv, t17.w, t.w);
        ob[(size_t)c * (HW / 4) + f4] = o;
    }
}

// ---------------------------------------------------------------------------
extern "C" void kernel_launch(void* const* d_in, const int* in_sizes, int n_in,
                              void* d_out, int out_size) {
    const float* x   = (const float*)d_in[0];
    const float* W2  = (const float*)d_in[1];
    const float* W8  = (const float*)d_in[2];
    const float* W10 = (const float*)d_in[3];
    const float* W18 = (const float*)d_in[4];
    const float* p4  = (const float*)d_in[5];
    const float* p13 = (const float*)d_in[6];
    float* out = (float*)d_out;

    kprep<<<200, 256>>>(W2, W8, W10);
    k1<<<NB * 32, 256>>>(x, p4);
    k2<<<NB * K25, 256>>>();
    k3k5<<<41 * 64, 256>>>(x, p13);          // k3 (compute) + x.t3 dot (memory)
    k5write<<<NB * 32, 256>>>(W18, out);
}